// round 9
// baseline (speedup 1.0000x reference)
#include <cuda_runtime.h>
#include <cstdint>

#define DN 128
#define CN 86
#define NP 96
#define NODE_TILE 64
#define ETILE 32            // edges per pipeline tile
#define ETHREADS 256
#define MAX_EDGES 1000000
#define PITCH 132

__device__ float g_P[100000 * 256];   // [n][0:128]=h@W1u+b1, [n][128:256]=h@W1v
__device__ int   g_src32[MAX_EDGES];
__device__ int   g_dst32[MAX_EDGES];
__device__ int   g_use64;
__device__ float g_W2T[NP * DN];      // W2^T [n][k], tf32-rounded, rows 86..95 = 0

// Edge-kernel smem float offsets (78592 B total -> 2 CTAs/SM)
#define OFF_U0   0                      // [32][132] = 4224
#define OFF_V0   4224
#define OFF_U1   8448
#define OFF_V1   12672
#define OFF_OUT  16896                  // [32][86]  = 2752
#define SMEM_EDGE_FLOATS 19648

__device__ __forceinline__ uint32_t f2tf32(float f) {
    uint32_t u;
    asm("cvt.rna.tf32.f32 %0, %1;" : "=r"(u) : "f"(f));
    return u;
}
__device__ __forceinline__ uint32_t smem_u32(const void* p) {
    uint32_t a;
    asm("{ .reg .u64 t; cvta.to.shared.u64 t, %1; cvt.u32.u64 %0, t; }"
        : "=r"(a) : "l"(p));
    return a;
}
__device__ __forceinline__ void cp16(uint32_t dst, const void* gsrc) {
    asm volatile("cp.async.cg.shared.global [%0], [%1], 16;"
                 :: "r"(dst), "l"(__cvta_generic_to_global(gsrc)) : "memory");
}
__device__ __forceinline__ void cp_commit() {
    asm volatile("cp.async.commit_group;" ::: "memory");
}
__device__ __forceinline__ void cp_wait1() {
    asm volatile("cp.async.wait_group 1;" ::: "memory");
}
__device__ __forceinline__ void mma_tf32(float* c, const uint32_t* a, const uint32_t* b) {
    asm volatile(
        "mma.sync.aligned.m16n8k8.row.col.f32.tf32.tf32.f32 "
        "{%0,%1,%2,%3}, {%4,%5,%6,%7}, {%8,%9}, {%0,%1,%2,%3};"
        : "+f"(c[0]), "+f"(c[1]), "+f"(c[2]), "+f"(c[3])
        : "r"(a[0]), "r"(a[1]), "r"(a[2]), "r"(a[3]), "r"(b[0]), "r"(b[1]));
}

// ---------------------------------------------------------------------------
// Prep kernels
// ---------------------------------------------------------------------------
__global__ void sniff_kernel(const void* src, int n_edges, int n_nodes)
{
    __shared__ int bad;
    if (threadIdx.x == 0) bad = 0;
    __syncthreads();
    const long long* p = (const long long*)src;
    int n_check = n_edges < 1024 ? n_edges : 1024;
    for (int i = threadIdx.x; i < n_check; i += blockDim.x) {
        long long v = p[i];
        if (v < 0 || v >= (long long)n_nodes) atomicOr(&bad, 1);
    }
    __syncthreads();
    if (threadIdx.x == 0) g_use64 = bad ? 0 : 1;
}

__global__ void convert_kernel(const void* src, const void* dst, int n_edges)
{
    int i = blockIdx.x * blockDim.x + threadIdx.x;
    if (i >= n_edges) return;
    if (g_use64) {
        g_src32[i] = (int)((const long long*)src)[i];
        g_dst32[i] = (int)((const long long*)dst)[i];
    } else {
        g_src32[i] = ((const int*)src)[i];
        g_dst32[i] = ((const int*)dst)[i];
    }
}

__global__ void w2t_kernel(const float* __restrict__ W2)
{
    int i = blockIdx.x * blockDim.x + threadIdx.x;
    if (i >= NP * DN) return;
    int n = i >> 7, k = i & 127;
    float v = (n < CN) ? W2[k * CN + n] : 0.f;
    g_W2T[i] = __uint_as_float(f2tf32(v));
}

// ---------------------------------------------------------------------------
// Kernel A: node GEMM (fp32 FFMA) — unchanged (188us).
// ---------------------------------------------------------------------------
__global__ void __launch_bounds__(256) node_gemm_kernel(
    const float* __restrict__ h, const float* __restrict__ W1,
    const float* __restrict__ b1, int n_nodes)
{
    extern __shared__ float sm[];
    float* As = sm;
    float* Bs = sm + 64 * 132;

    const int n0 = blockIdx.x * NODE_TILE;
    const int tid = threadIdx.x;
    const int tx = tid & 15;
    const int ty = tid >> 4;

    #pragma unroll
    for (int i = tid; i < NODE_TILE * 32; i += 256) {
        int r = i >> 5, v = i & 31;
        float4 val = make_float4(0.f, 0.f, 0.f, 0.f);
        if (n0 + r < n_nodes)
            val = *reinterpret_cast<const float4*>(&h[(size_t)(n0 + r) * DN + 4 * v]);
        *reinterpret_cast<float4*>(&As[r * 132 + 4 * v]) = val;
    }

    float acc[4][16];
    #pragma unroll
    for (int j = 0; j < 4; j++)
        #pragma unroll
        for (int c = 0; c < 16; c++) acc[j][c] = 0.f;

    for (int kc = 0; kc < DN; kc += 16) {
        __syncthreads();
        #pragma unroll
        for (int i = tid; i < 16 * 64; i += 256) {
            int r = i >> 6, v = i & 63;
            int j = v * 4;
            const float* srcp = (j < DN) ? &W1[(size_t)(kc + r) * DN + j]
                                         : &W1[(size_t)(DN + kc + r) * DN + (j - DN)];
            *reinterpret_cast<float4*>(&Bs[r * 256 + j]) =
                *reinterpret_cast<const float4*>(srcp);
        }
        __syncthreads();

        #pragma unroll
        for (int k = 0; k < 16; k++) {
            float a[4], b[16];
            #pragma unroll
            for (int j = 0; j < 4; j++) a[j] = As[(ty * 4 + j) * 132 + kc + k];
            #pragma unroll
            for (int c = 0; c < 16; c++) b[c] = Bs[k * 256 + tx + 16 * c];
            #pragma unroll
            for (int j = 0; j < 4; j++)
                #pragma unroll
                for (int c = 0; c < 16; c++)
                    acc[j][c] = fmaf(a[j], b[c], acc[j][c]);
        }
    }

    #pragma unroll
    for (int j = 0; j < 4; j++) {
        int node = n0 + ty * 4 + j;
        if (node < n_nodes) {
            #pragma unroll
            for (int c = 0; c < 16; c++) {
                int col = tx + 16 * c;
                float v = acc[j][c];
                if (col < DN) v += b1[col];
                g_P[(size_t)node * 256 + col] = v;
            }
        }
    }
}

// ---------------------------------------------------------------------------
// Kernel B: persistent pipelined edge MLP, 2 CTAs/SM.
// ETILE=32, 256 threads / 8 warps. Warp tile: wr=wid&1 (16 rows),
// wc=wid>>1 (24 cols = 3 n8-tiles). W2 fragments read from global (L1-hot).
// U/V double-buffered cp.async.
// ---------------------------------------------------------------------------
__global__ void __launch_bounds__(ETHREADS) edge_mma_kernel(
    const float* __restrict__ b2, float* __restrict__ out,
    int n_edges, int n_tiles)
{
    extern __shared__ float sm[];
    float* Ubuf[2] = { sm + OFF_U0, sm + OFF_U1 };
    float* Vbuf[2] = { sm + OFF_V0, sm + OFF_V1 };
    float* OUTS = sm + OFF_OUT;

    const int tid  = threadIdx.x;
    const int wid  = tid >> 5;
    const int lane = tid & 31;
    const int G    = gridDim.x;

    const uint32_t u_s32[2] = { smem_u32(Ubuf[0]), smem_u32(Ubuf[1]) };
    const uint32_t v_s32[2] = { smem_u32(Vbuf[0]), smem_u32(Vbuf[1]) };

    const int e_loc = tid >> 3;          // 0..31
    const int q     = tid & 7;           // 16-float slice within 128-float row

    auto prefetch = [&](int t, int stg) {
        if (t < n_tiles) {
            int eg = t * ETILE + e_loc;
            int s = 0, d = 0;
            if (eg < n_edges) { s = __ldg(&g_src32[eg]); d = __ldg(&g_dst32[eg]); }
            const float* usrc = &g_P[(size_t)s * 256 + q * 16];
            const float* vsrc = &g_P[(size_t)d * 256 + 128 + q * 16];
            uint32_t udst = u_s32[stg] + (e_loc * PITCH + q * 16) * 4;
            uint32_t vdst = v_s32[stg] + (e_loc * PITCH + q * 16) * 4;
            #pragma unroll
            for (int c2 = 0; c2 < 4; c2++) {
                cp16(udst + c2 * 16, usrc + c2 * 4);
                cp16(vdst + c2 * 16, vsrc + c2 * 4);
            }
        }
        cp_commit();
    };

    const int wr = wid & 1;        // row group (16 edges)
    const int wc = wid >> 1;       // col group (24 cols)
    const int arow = wr * 16 + (lane >> 2);
    const int bcol = wc * 24 + (lane >> 2);
    const int kq   = lane & 3;

    int stage = 0;
    prefetch(blockIdx.x, 0);

    for (int t = blockIdx.x; t < n_tiles; t += G) {
        prefetch(t + G, stage ^ 1);
        cp_wait1();              // tile t resident
        __syncthreads();

        // relu-add in place: U = tf32(relu(U+V))
        {
            float* up = &Ubuf[stage][e_loc * PITCH + q * 16];
            const float* vp = &Vbuf[stage][e_loc * PITCH + q * 16];
            #pragma unroll
            for (int c2 = 0; c2 < 4; c2++) {
                float4 u = *reinterpret_cast<const float4*>(up + 4 * c2);
                float4 v = *reinterpret_cast<const float4*>(vp + 4 * c2);
                u.x = __uint_as_float(f2tf32(fmaxf(u.x + v.x, 0.f)));
                u.y = __uint_as_float(f2tf32(fmaxf(u.y + v.y, 0.f)));
                u.z = __uint_as_float(f2tf32(fmaxf(u.z + v.z, 0.f)));
                u.w = __uint_as_float(f2tf32(fmaxf(u.w + v.w, 0.f)));
                *reinterpret_cast<float4*>(up + 4 * c2) = u;
            }
        }
        __syncthreads();

        // MMA 32x96x128: per warp 1 m16-tile x 3 n8-tiles.
        // B fragments from g_W2T (global, L1-resident; cp.async.cg bypasses L1).
        float c[3][4];
        #pragma unroll
        for (int i = 0; i < 3; i++)
            #pragma unroll
            for (int r = 0; r < 4; r++) c[i][r] = 0.f;

        const float* Ub = Ubuf[stage];
        #pragma unroll
        for (int kk = 0; kk < 16; kk++) {
            const int k0 = kk * 8 + kq;
            uint32_t a[4];
            {
                const float* p = &Ub[arow * PITCH + k0];
                a[0] = __float_as_uint(p[0]);
                a[1] = __float_as_uint(p[8 * PITCH]);
                a[2] = __float_as_uint(p[4]);
                a[3] = __float_as_uint(p[8 * PITCH + 4]);
            }
            uint32_t b[3][2];
            #pragma unroll
            for (int j = 0; j < 3; j++) {
                const float* p = &g_W2T[(bcol + j * 8) * DN + k0];
                b[j][0] = __float_as_uint(__ldg(p));
                b[j][1] = __float_as_uint(__ldg(p + 4));
            }
            #pragma unroll
            for (int j = 0; j < 3; j++)
                mma_tf32(c[j], a, b[j]);
        }

        // Epilogue: fragments -> OUTS [32][86], then coalesced store.
        {
            const int row = wr * 16 + (lane >> 2);
            const int cb  = 2 * (lane & 3);
            #pragma unroll
            for (int j = 0; j < 3; j++) {
                int col = wc * 24 + j * 8 + cb;
                #pragma unroll
                for (int r = 0; r < 4; r++) {
                    int cc = col + (r & 1);
                    int rr = row + ((r >> 1) << 3);
                    if (cc < CN)
                        OUTS[rr * CN + cc] = c[j][r] + b2[cc];
                }
            }
        }
        __syncthreads();

        int e0 = t * ETILE;
        int valid = n_edges - e0;
        if (valid > ETILE) valid = ETILE;
        float* dstp = out + (size_t)e0 * CN;
        if (valid == ETILE) {
            const float4* s4 = reinterpret_cast<const float4*>(OUTS);
            float4* d4 = reinterpret_cast<float4*>(dstp);
            #pragma unroll
            for (int i = tid; i < ETILE * CN / 4; i += ETHREADS) d4[i] = s4[i];
        } else {
            for (int i = tid; i < valid * CN; i += ETHREADS) dstp[i] = OUTS[i];
        }
        __syncthreads();
        stage ^= 1;
    }
}

// ---------------------------------------------------------------------------
extern "C" void kernel_launch(void* const* d_in, const int* in_sizes, int n_in,
                              void* d_out, int out_size)
{
    const float* h   = (const float*)d_in[0];
    const float* W1  = (const float*)d_in[1];
    const float* b1  = (const float*)d_in[2];
    const float* W2  = (const float*)d_in[3];
    const float* b2  = (const float*)d_in[4];
    const void*  src = d_in[5];
    const void*  dst = d_in[6];
    float* out = (float*)d_out;

    const int n_nodes = in_sizes[0] / DN;
    const int n_edges = in_sizes[5];

    static int n_sm = 0;
    if (n_sm == 0) {
        cudaDeviceGetAttribute(&n_sm, cudaDevAttrMultiProcessorCount, 0);
        if (n_sm <= 0) n_sm = 148;
    }

    sniff_kernel<<<1, 256>>>(src, n_edges, n_nodes);
    convert_kernel<<<(n_edges + 255) / 256, 256>>>(src, dst, n_edges);
    w2t_kernel<<<(NP * DN + 255) / 256, 256>>>(W2);

    const int smemA = (64 * 132 + 16 * 256) * sizeof(float);
    const int smemB = SMEM_EDGE_FLOATS * sizeof(float);   // 78592
    cudaFuncSetAttribute(node_gemm_kernel, cudaFuncAttributeMaxDynamicSharedMemorySize, smemA);
    cudaFuncSetAttribute(edge_mma_kernel,  cudaFuncAttributeMaxDynamicSharedMemorySize, smemB);

    int gridA = (n_nodes + NODE_TILE - 1) / NODE_TILE;
    node_gemm_kernel<<<gridA, 256, smemA>>>(h, W1, b1, n_nodes);

    int n_tiles = (n_edges + ETILE - 1) / ETILE;
    edge_mma_kernel<<<2 * n_sm, ETHREADS, smemB>>>(b2, out, n_edges, n_tiles);
}

// round 10
// speedup vs baseline: 3.1832x; 3.1832x over previous
#include <cuda_runtime.h>
#include <cuda_fp16.h>
#include <cstdint>

#define DN 128
#define CN 86
#define NP 96
#define NODE_TILE 64
#define ETILE 64
#define ETHREADS 512
#define MAX_EDGES 1000000

__device__ __half g_P16[100000 * 256];   // [n][0:128]=h@W1u+b1, [n][128:256]=h@W1v (fp16)
__device__ int    g_src32[MAX_EDGES];
__device__ int    g_dst32[MAX_EDGES];
__device__ int    g_use64;
__device__ __half g_W2H[NP * DN];        // W2^T [n][k] fp16, rows 86..95 = 0

// Edge smem layout (bytes): 3 stages x (U 17408 + V 17408), then OUTS fp32.
#define STAGE_BYTES 34816                 // U+V per stage
#define U_PITCH_B   272                   // 136 fp16 per row
#define OFF_OUTS    104448                // 3*34816
#define SMEM_EDGE_BYTES (104448 + 64 * CN * 4)   // 126464

__device__ __forceinline__ uint32_t smem_u32(const void* p) {
    uint32_t a;
    asm("{ .reg .u64 t; cvta.to.shared.u64 t, %1; cvt.u32.u64 %0, t; }"
        : "=r"(a) : "l"(p));
    return a;
}
__device__ __forceinline__ void cp16(uint32_t dst, const void* gsrc) {
    asm volatile("cp.async.cg.shared.global [%0], [%1], 16;"
                 :: "r"(dst), "l"(__cvta_generic_to_global(gsrc)) : "memory");
}
__device__ __forceinline__ void cp_commit() {
    asm volatile("cp.async.commit_group;" ::: "memory");
}
__device__ __forceinline__ void cp_wait2() {
    asm volatile("cp.async.wait_group 2;" ::: "memory");
}
__device__ __forceinline__ void cp_wait0() {
    asm volatile("cp.async.wait_group 0;" ::: "memory");
}
__device__ __forceinline__ void ldmx4(uint32_t* r, uint32_t addr) {
    asm volatile("ldmatrix.sync.aligned.m8n8.x4.shared.b16 {%0,%1,%2,%3}, [%4];"
                 : "=r"(r[0]), "=r"(r[1]), "=r"(r[2]), "=r"(r[3]) : "r"(addr));
}
__device__ __forceinline__ uint32_t hadd2_(uint32_t a, uint32_t b) {
    uint32_t d; asm("add.f16x2 %0, %1, %2;" : "=r"(d) : "r"(a), "r"(b)); return d;
}
__device__ __forceinline__ uint32_t hrelu2_(uint32_t a) {
    uint32_t d; asm("max.f16x2 %0, %1, %2;" : "=r"(d) : "r"(a), "r"(0u)); return d;
}
__device__ __forceinline__ void mma_f16(float* c, const uint32_t* a, const uint32_t* b) {
    asm volatile(
        "mma.sync.aligned.m16n8k16.row.col.f32.f16.f16.f32 "
        "{%0,%1,%2,%3}, {%4,%5,%6,%7}, {%8,%9}, {%0,%1,%2,%3};"
        : "+f"(c[0]), "+f"(c[1]), "+f"(c[2]), "+f"(c[3])
        : "r"(a[0]), "r"(a[1]), "r"(a[2]), "r"(a[3]), "r"(b[0]), "r"(b[1]));
}

// ---------------------------------------------------------------------------
// Prep kernels
// ---------------------------------------------------------------------------
__global__ void sniff_kernel(const void* src, int n_edges, int n_nodes)
{
    __shared__ int bad;
    if (threadIdx.x == 0) bad = 0;
    __syncthreads();
    const long long* p = (const long long*)src;
    int n_check = n_edges < 1024 ? n_edges : 1024;
    for (int i = threadIdx.x; i < n_check; i += blockDim.x) {
        long long v = p[i];
        if (v < 0 || v >= (long long)n_nodes) atomicOr(&bad, 1);
    }
    __syncthreads();
    if (threadIdx.x == 0) g_use64 = bad ? 0 : 1;
}

__global__ void convert_kernel(const void* src, const void* dst, int n_edges)
{
    int i = blockIdx.x * blockDim.x + threadIdx.x;
    if (i >= n_edges) return;
    if (g_use64) {
        g_src32[i] = (int)((const long long*)src)[i];
        g_dst32[i] = (int)((const long long*)dst)[i];
    } else {
        g_src32[i] = ((const int*)src)[i];
        g_dst32[i] = ((const int*)dst)[i];
    }
}

__global__ void w2h_kernel(const float* __restrict__ W2)
{
    int i = blockIdx.x * blockDim.x + threadIdx.x;
    if (i >= NP * DN) return;
    int n = i >> 7, k = i & 127;
    float v = (n < CN) ? W2[k * CN + n] : 0.f;
    g_W2H[i] = __float2half_rn(v);
}

// ---------------------------------------------------------------------------
// Kernel A: node GEMM (fp32 FFMA), stores P as fp16.
// ---------------------------------------------------------------------------
__global__ void __launch_bounds__(256) node_gemm_kernel(
    const float* __restrict__ h, const float* __restrict__ W1,
    const float* __restrict__ b1, int n_nodes)
{
    extern __shared__ float sm[];
    float* As = sm;                  // [64][132]
    float* Bs = sm + 64 * 132;       // [16][256]

    const int n0 = blockIdx.x * NODE_TILE;
    const int tid = threadIdx.x;
    const int tx = tid & 15;
    const int ty = tid >> 4;

    #pragma unroll
    for (int i = tid; i < NODE_TILE * 32; i += 256) {
        int r = i >> 5, v = i & 31;
        float4 val = make_float4(0.f, 0.f, 0.f, 0.f);
        if (n0 + r < n_nodes)
            val = *reinterpret_cast<const float4*>(&h[(size_t)(n0 + r) * DN + 4 * v]);
        *reinterpret_cast<float4*>(&As[r * 132 + 4 * v]) = val;
    }

    float acc[4][16];
    #pragma unroll
    for (int j = 0; j < 4; j++)
        #pragma unroll
        for (int c = 0; c < 16; c++) acc[j][c] = 0.f;

    for (int kc = 0; kc < DN; kc += 16) {
        __syncthreads();
        #pragma unroll
        for (int i = tid; i < 16 * 64; i += 256) {
            int r = i >> 6, v = i & 63;
            int j = v * 4;
            const float* srcp = (j < DN) ? &W1[(size_t)(kc + r) * DN + j]
                                         : &W1[(size_t)(DN + kc + r) * DN + (j - DN)];
            *reinterpret_cast<float4*>(&Bs[r * 256 + j]) =
                *reinterpret_cast<const float4*>(srcp);
        }
        __syncthreads();

        #pragma unroll
        for (int k = 0; k < 16; k++) {
            float a[4], b[16];
            #pragma unroll
            for (int j = 0; j < 4; j++) a[j] = As[(ty * 4 + j) * 132 + kc + k];
            #pragma unroll
            for (int c = 0; c < 16; c++) b[c] = Bs[k * 256 + tx + 16 * c];
            #pragma unroll
            for (int j = 0; j < 4; j++)
                #pragma unroll
                for (int c = 0; c < 16; c++)
                    acc[j][c] = fmaf(a[j], b[c], acc[j][c]);
        }
    }

    #pragma unroll
    for (int j = 0; j < 4; j++) {
        int node = n0 + ty * 4 + j;
        if (node < n_nodes) {
            #pragma unroll
            for (int c = 0; c < 16; c++) {
                int col = tx + 16 * c;
                float v = acc[j][c];
                if (col < DN) v += b1[col];
                g_P16[(size_t)node * 256 + col] = __float2half_rn(v);
            }
        }
    }
}

// ---------------------------------------------------------------------------
// Kernel B: persistent fp16 edge MLP. Depth-3 cp.async pipeline, ETILE=64.
// 16 warps: wr=wid&3 (16 rows), wc=wid>>2 (24 cols = 3 n8-tiles).
// W2 fragments live in registers; relu-add fused on ldmatrix fragments.
// ---------------------------------------------------------------------------
__global__ void __launch_bounds__(ETHREADS) edge_mma_kernel(
    const float* __restrict__ b2, float* __restrict__ out,
    int n_edges, int n_tiles)
{
    extern __shared__ char smem[];
    const uint32_t sbase = smem_u32(smem);
    float* OUTS = reinterpret_cast<float*>(smem + OFF_OUTS);

    const int tid  = threadIdx.x;
    const int wid  = tid >> 5;
    const int lane = tid & 31;
    const int G    = gridDim.x;

    const int e_loc = tid >> 3;     // 0..63
    const int q     = tid & 7;      // 16-fp16 slice of a 128-fp16 row

    const int wr = wid & 3;         // row group (16 edges)
    const int wc = wid >> 2;        // col group (24 cols)
    const int arow0 = wr * 16;

    // Preload W2 fragments into registers: bf[j][kk][2].
    uint32_t bf[3][8][2];
    {
        const int n = wc * 24 + (lane >> 2);          // < 96 always
        const int k2 = 2 * (lane & 3);
        #pragma unroll
        for (int j = 0; j < 3; j++) {
            const __half* rowp = &g_W2H[(n + j * 8) * DN];
            #pragma unroll
            for (int kk = 0; kk < 8; kk++) {
                bf[j][kk][0] = *reinterpret_cast<const uint32_t*>(rowp + kk * 16 + k2);
                bf[j][kk][1] = *reinterpret_cast<const uint32_t*>(rowp + kk * 16 + k2 + 8);
            }
        }
    }
    // Preload bias for this thread's output columns.
    float bias[3][2];
    {
        #pragma unroll
        for (int j = 0; j < 3; j++) {
            int col = wc * 24 + j * 8 + 2 * (lane & 3);
            bias[j][0] = (col     < CN) ? b2[col]     : 0.f;
            bias[j][1] = (col + 1 < CN) ? b2[col + 1] : 0.f;
        }
    }

    auto prefetch = [&](int t, int s) {
        if (t < n_tiles) {
            int eg = t * ETILE + e_loc;
            int si = 0, di = 0;
            if (eg < n_edges) { si = __ldg(&g_src32[eg]); di = __ldg(&g_dst32[eg]); }
            const __half* us = &g_P16[(size_t)si * 256 + q * 16];
            const __half* vs = &g_P16[(size_t)di * 256 + 128 + q * 16];
            uint32_t ud = sbase + s * STAGE_BYTES + e_loc * U_PITCH_B + q * 32;
            uint32_t vd = ud + 17408;
            cp16(ud,      us);
            cp16(ud + 16, us + 8);
            cp16(vd,      vs);
            cp16(vd + 16, vs + 8);
        }
        cp_commit();
    };

    // ldmatrix lane address offset within a U/V buffer (depends on lane, kk).
    const int lrow = lane & 15;
    const int lkof = (lane >> 4) * 16;   // bytes (8 fp16)
    const uint32_t a_off = (uint32_t)(arow0 + lrow) * U_PITCH_B + lkof;

    int stage = 0;
    prefetch(blockIdx.x, 0);
    prefetch(blockIdx.x + G, 1);

    for (int t = blockIdx.x; t < n_tiles; t += G) {
        prefetch(t + 2 * G, (stage + 2) % 3);
        cp_wait2();
        __syncthreads();

        const uint32_t ub = sbase + stage * STAGE_BYTES + a_off;
        const uint32_t vb = ub + 17408;

        float c[3][4];
        #pragma unroll
        for (int j = 0; j < 3; j++)
            #pragma unroll
            for (int r = 0; r < 4; r++) c[j][r] = 0.f;

        #pragma unroll
        for (int kk = 0; kk < 8; kk++) {
            uint32_t au[4], av[4], a[4];
            ldmx4(au, ub + kk * 32);
            ldmx4(av, vb + kk * 32);
            #pragma unroll
            for (int r = 0; r < 4; r++)
                a[r] = hrelu2_(hadd2_(au[r], av[r]));
            #pragma unroll
            for (int j = 0; j < 3; j++)
                mma_f16(c[j], a, bf[j][kk]);
        }
        __syncthreads();   // all reads of U/V[stage] done before reuse

        // Epilogue: fragments -> OUTS [64][86].
        {
            const int row = arow0 + (lane >> 2);
            #pragma unroll
            for (int j = 0; j < 3; j++) {
                int col = wc * 24 + j * 8 + 2 * (lane & 3);
                if (col < CN) {
                    OUTS[row * CN + col]       = c[j][0] + bias[j][0];
                    OUTS[(row + 8) * CN + col] = c[j][2] + bias[j][0];
                }
                if (col + 1 < CN) {
                    OUTS[row * CN + col + 1]       = c[j][1] + bias[j][1];
                    OUTS[(row + 8) * CN + col + 1] = c[j][3] + bias[j][1];
                }
            }
        }
        __syncthreads();

        int e0 = t * ETILE;
        int valid = n_edges - e0;
        if (valid > ETILE) valid = ETILE;
        float* dstp = out + (size_t)e0 * CN;
        if (valid == ETILE) {
            const float4* s4 = reinterpret_cast<const float4*>(OUTS);
            float4* d4 = reinterpret_cast<float4*>(dstp);
            #pragma unroll
            for (int i = tid; i < ETILE * CN / 4; i += ETHREADS) d4[i] = s4[i];
        } else {
            for (int i = tid; i < valid * CN; i += ETHREADS) dstp[i] = OUTS[i];
        }
        __syncthreads();
        stage = (stage + 1) % 3;
    }
    cp_wait0();   // drain any remaining async groups before exit
}

// ---------------------------------------------------------------------------
extern "C" void kernel_launch(void* const* d_in, const int* in_sizes, int n_in,
                              void* d_out, int out_size)
{
    const float* h   = (const float*)d_in[0];
    const float* W1  = (const float*)d_in[1];
    const float* b1  = (const float*)d_in[2];
    const float* W2  = (const float*)d_in[3];
    const float* b2  = (const float*)d_in[4];
    const void*  src = d_in[5];
    const void*  dst = d_in[6];
    float* out = (float*)d_out;

    const int n_nodes = in_sizes[0] / DN;
    const int n_edges = in_sizes[5];

    static int n_sm = 0;
    if (n_sm == 0) {
        cudaDeviceGetAttribute(&n_sm, cudaDevAttrMultiProcessorCount, 0);
        if (n_sm <= 0) n_sm = 148;
    }

    sniff_kernel<<<1, 256>>>(src, n_edges, n_nodes);
    convert_kernel<<<(n_edges + 255) / 256, 256>>>(src, dst, n_edges);
    w2h_kernel<<<(NP * DN + 255) / 256, 256>>>(W2);

    const int smemA = (64 * 132 + 16 * 256) * sizeof(float);
    cudaFuncSetAttribute(node_gemm_kernel, cudaFuncAttributeMaxDynamicSharedMemorySize, smemA);
    cudaFuncSetAttribute(edge_mma_kernel,  cudaFuncAttributeMaxDynamicSharedMemorySize, SMEM_EDGE_BYTES);

    int gridA = (n_nodes + NODE_TILE - 1) / NODE_TILE;
    node_gemm_kernel<<<gridA, 256, smemA>>>(h, W1, b1, n_nodes);

    int n_tiles = (n_edges + ETILE - 1) / ETILE;
    edge_mma_kernel<<<n_sm, ETHREADS, SMEM_EDGE_BYTES>>>(b2, out, n_edges, n_tiles);
}

// round 11
// speedup vs baseline: 4.4965x; 1.4126x over previous
#include <cuda_runtime.h>
#include <cuda_fp16.h>
#include <cstdint>

#define DN 128
#define CN 86
#define NP 96
#define ETILE 64
#define ETHREADS 512
#define MAX_EDGES 1000000

__device__ __half g_P16[100000 * 256];   // [n][0:128]=h@W1u+b1, [n][128:256]=h@W1v (fp16)
__device__ __half g_H16[100000 * 128];   // h in fp16
__device__ int    g_src32[MAX_EDGES];
__device__ int    g_dst32[MAX_EDGES];
__device__ int    g_use64;
__device__ __half g_W2H[NP * DN];        // W2^T [n][k] fp16, rows 86..95 = 0

// ---- edge kernel smem (unchanged from R10) ----
#define STAGE_BYTES 34816
#define U_PITCH_B   272
#define OFF_OUTS    104448
#define SMEM_EDGE_BYTES (104448 + 64 * CN * 4)

// ---- node kernel smem ----
#define W1_PITCH_B  272                  // 136 fp16 per row
#define OFF_W1H     0                    // [256][136] fp16 = 69632 B
#define OFF_HST     69632                // 2 stages x [64][136] fp16 (17408 B each)
#define HSTAGE_B    17408
#define SMEM_NODE_BYTES (69632 + 2 * 17408)   // 104448

__device__ __forceinline__ uint32_t smem_u32(const void* p) {
    uint32_t a;
    asm("{ .reg .u64 t; cvta.to.shared.u64 t, %1; cvt.u32.u64 %0, t; }"
        : "=r"(a) : "l"(p));
    return a;
}
__device__ __forceinline__ void cp16(uint32_t dst, const void* gsrc) {
    asm volatile("cp.async.cg.shared.global [%0], [%1], 16;"
                 :: "r"(dst), "l"(__cvta_generic_to_global(gsrc)) : "memory");
}
__device__ __forceinline__ void cp_commit() {
    asm volatile("cp.async.commit_group;" ::: "memory");
}
__device__ __forceinline__ void cp_wait1() {
    asm volatile("cp.async.wait_group 1;" ::: "memory");
}
__device__ __forceinline__ void cp_wait2() {
    asm volatile("cp.async.wait_group 2;" ::: "memory");
}
__device__ __forceinline__ void cp_wait0() {
    asm volatile("cp.async.wait_group 0;" ::: "memory");
}
__device__ __forceinline__ void ldmx4(uint32_t* r, uint32_t addr) {
    asm volatile("ldmatrix.sync.aligned.m8n8.x4.shared.b16 {%0,%1,%2,%3}, [%4];"
                 : "=r"(r[0]), "=r"(r[1]), "=r"(r[2]), "=r"(r[3]) : "r"(addr));
}
__device__ __forceinline__ uint32_t hadd2_(uint32_t a, uint32_t b) {
    uint32_t d; asm("add.f16x2 %0, %1, %2;" : "=r"(d) : "r"(a), "r"(b)); return d;
}
__device__ __forceinline__ uint32_t hrelu2_(uint32_t a) {
    uint32_t d; asm("max.f16x2 %0, %1, %2;" : "=r"(d) : "r"(a), "r"(0u)); return d;
}
__device__ __forceinline__ void mma_f16(float* c, const uint32_t* a, const uint32_t* b) {
    asm volatile(
        "mma.sync.aligned.m16n8k16.row.col.f32.f16.f16.f32 "
        "{%0,%1,%2,%3}, {%4,%5,%6,%7}, {%8,%9}, {%0,%1,%2,%3};"
        : "+f"(c[0]), "+f"(c[1]), "+f"(c[2]), "+f"(c[3])
        : "r"(a[0]), "r"(a[1]), "r"(a[2]), "r"(a[3]), "r"(b[0]), "r"(b[1]));
}

// ---------------------------------------------------------------------------
// Prep kernels
// ---------------------------------------------------------------------------
__global__ void sniff_kernel(const void* src, int n_edges, int n_nodes)
{
    __shared__ int bad;
    if (threadIdx.x == 0) bad = 0;
    __syncthreads();
    const long long* p = (const long long*)src;
    int n_check = n_edges < 1024 ? n_edges : 1024;
    for (int i = threadIdx.x; i < n_check; i += blockDim.x) {
        long long v = p[i];
        if (v < 0 || v >= (long long)n_nodes) atomicOr(&bad, 1);
    }
    __syncthreads();
    if (threadIdx.x == 0) g_use64 = bad ? 0 : 1;
}

__global__ void convert_kernel(const void* src, const void* dst, int n_edges)
{
    int i = blockIdx.x * blockDim.x + threadIdx.x;
    if (i >= n_edges) return;
    if (g_use64) {
        g_src32[i] = (int)((const long long*)src)[i];
        g_dst32[i] = (int)((const long long*)dst)[i];
    } else {
        g_src32[i] = ((const int*)src)[i];
        g_dst32[i] = ((const int*)dst)[i];
    }
}

__global__ void w2h_kernel(const float* __restrict__ W2)
{
    int i = blockIdx.x * blockDim.x + threadIdx.x;
    if (i >= NP * DN) return;
    int n = i >> 7, k = i & 127;
    float v = (n < CN) ? W2[k * CN + n] : 0.f;
    g_W2H[i] = __float2half_rn(v);
}

__global__ void h16_kernel(const float* __restrict__ h, int n_elem)
{
    int i = (blockIdx.x * blockDim.x + threadIdx.x) * 4;
    if (i >= n_elem) return;
    float4 v = *reinterpret_cast<const float4*>(&h[i]);
    __half2 lo = __floats2half2_rn(v.x, v.y);
    __half2 hi = __floats2half2_rn(v.z, v.w);
    uint2 bits = make_uint2(*reinterpret_cast<uint32_t*>(&lo),
                            *reinterpret_cast<uint32_t*>(&hi));
    *reinterpret_cast<uint2*>(&g_H16[i]) = bits;
}

// ---------------------------------------------------------------------------
// Kernel A: node GEMM on fp16 mma.sync. Persistent; W1 fused tile in smem.
// Tile = 64 nodes x 256 cols, K=128. 512 threads, 16 warps:
// wr=wid&3 (16 rows), wc=wid>>2 (64 cols = 8 n8-tiles).
// ---------------------------------------------------------------------------
__global__ void __launch_bounds__(512) node_mma_kernel(
    const float* __restrict__ W1, const float* __restrict__ b1,
    int n_nodes, int n_tiles)
{
    extern __shared__ char smem[];
    const uint32_t sbase = smem_u32(smem);
    __half* W1s = reinterpret_cast<__half*>(smem + OFF_W1H);

    const int tid  = threadIdx.x;
    const int wid  = tid >> 5;
    const int lane = tid & 31;
    const int G    = gridDim.x;

    // Stage fused W1' [n=256][k=128] fp16 once (pitch 136 halves).
    for (int i = tid; i < 256 * 128; i += 512) {
        int k = i >> 8, n = i & 255;
        float v = (n < DN) ? W1[(size_t)k * DN + n]
                           : W1[(size_t)(DN + k) * DN + (n - DN)];
        W1s[n * 136 + k] = __float2half_rn(v);
    }

    const int wr = wid & 3;
    const int wc = wid >> 2;
    const int arow0 = wr * 16;

    // bias: cols < 128 get b1 (wc 0,1 only)
    float bias[8][2];
    #pragma unroll
    for (int j = 0; j < 8; j++) {
        int col = wc * 64 + j * 8 + 2 * (lane & 3);
        bias[j][0] = (col     < DN) ? b1[col]     : 0.f;
        bias[j][1] = (col + 1 < DN) ? b1[col + 1] : 0.f;
    }

    const int e_loc = tid >> 3;      // 0..63 (node row in tile)
    const int q     = tid & 7;       // 16-fp16 slice

    auto prefetch = [&](int t, int s) {
        if (t < n_tiles) {
            int node = t * 64 + e_loc;
            if (node >= n_nodes) node = 0;
            const __half* hs = &g_H16[(size_t)node * 128 + q * 16];
            uint32_t hd = sbase + OFF_HST + s * HSTAGE_B + e_loc * W1_PITCH_B + q * 32;
            cp16(hd,      hs);
            cp16(hd + 16, hs + 8);
        }
        cp_commit();
    };

    // A ldmatrix lane offset; B ldmatrix lane offset.
    const uint32_t a_off = (uint32_t)(arow0 + (lane & 15)) * W1_PITCH_B + (lane >> 4) * 16;
    const uint32_t b_row = (uint32_t)(wc * 64 + (lane & 7) + ((lane >> 4) & 1) * 8);
    const uint32_t b_off = b_row * W1_PITCH_B + ((lane >> 3) & 1) * 16;
    const uint32_t wb    = sbase + OFF_W1H + b_off;

    __syncthreads();   // W1s ready

    int stage = 0;
    prefetch(blockIdx.x, 0);

    for (int t = blockIdx.x; t < n_tiles; t += G) {
        prefetch(t + G, stage ^ 1);
        cp_wait1();
        __syncthreads();

        const uint32_t ub = sbase + OFF_HST + stage * HSTAGE_B + a_off;

        float c[8][4];
        #pragma unroll
        for (int j = 0; j < 8; j++)
            #pragma unroll
            for (int r = 0; r < 4; r++) c[j][r] = 0.f;

        #pragma unroll
        for (int kk = 0; kk < 8; kk++) {
            uint32_t a[4];
            ldmx4(a, ub + kk * 32);
            #pragma unroll
            for (int p = 0; p < 4; p++) {
                uint32_t bq[4];
                ldmx4(bq, wb + p * 16 * W1_PITCH_B + kk * 32);
                mma_f16(c[2 * p],     a, bq);
                mma_f16(c[2 * p + 1], a, bq + 2);
            }
        }

        // Epilogue: fragments (+b1) -> fp16 -> g_P16 directly.
        {
            const int r0 = t * 64 + arow0 + (lane >> 2);
            #pragma unroll
            for (int j = 0; j < 8; j++) {
                int col = wc * 64 + j * 8 + 2 * (lane & 3);
                if (r0 < n_nodes) {
                    __half2 v = __floats2half2_rn(c[j][0] + bias[j][0],
                                                  c[j][1] + bias[j][1]);
                    *reinterpret_cast<uint32_t*>(&g_P16[(size_t)r0 * 256 + col]) =
                        *reinterpret_cast<uint32_t*>(&v);
                }
                if (r0 + 8 < n_nodes) {
                    __half2 v = __floats2half2_rn(c[j][2] + bias[j][0],
                                                  c[j][3] + bias[j][1]);
                    *reinterpret_cast<uint32_t*>(&g_P16[(size_t)(r0 + 8) * 256 + col]) =
                        *reinterpret_cast<uint32_t*>(&v);
                }
            }
        }
        __syncthreads();   // all ldmatrix reads of this stage done
        stage ^= 1;
    }
    cp_wait0();
}

// ---------------------------------------------------------------------------
// Kernel B: persistent fp16 edge MLP (unchanged from R10).
// ---------------------------------------------------------------------------
__global__ void __launch_bounds__(ETHREADS) edge_mma_kernel(
    const float* __restrict__ b2, float* __restrict__ out,
    int n_edges, int n_tiles)
{
    extern __shared__ char smem[];
    const uint32_t sbase = smem_u32(smem);
    float* OUTS = reinterpret_cast<float*>(smem + OFF_OUTS);

    const int tid  = threadIdx.x;
    const int wid  = tid >> 5;
    const int lane = tid & 31;
    const int G    = gridDim.x;

    const int e_loc = tid >> 3;
    const int q     = tid & 7;

    const int wr = wid & 3;
    const int wc = wid >> 2;
    const int arow0 = wr * 16;

    uint32_t bf[3][8][2];
    {
        const int n = wc * 24 + (lane >> 2);
        const int k2 = 2 * (lane & 3);
        #pragma unroll
        for (int j = 0; j < 3; j++) {
            const __half* rowp = &g_W2H[(n + j * 8) * DN];
            #pragma unroll
            for (int kk = 0; kk < 8; kk++) {
                bf[j][kk][0] = *reinterpret_cast<const uint32_t*>(rowp + kk * 16 + k2);
                bf[j][kk][1] = *reinterpret_cast<const uint32_t*>(rowp + kk * 16 + k2 + 8);
            }
        }
    }
    float bias[3][2];
    #pragma unroll
    for (int j = 0; j < 3; j++) {
        int col = wc * 24 + j * 8 + 2 * (lane & 3);
        bias[j][0] = (col     < CN) ? b2[col]     : 0.f;
        bias[j][1] = (col + 1 < CN) ? b2[col + 1] : 0.f;
    }

    auto prefetch = [&](int t, int s) {
        if (t < n_tiles) {
            int eg = t * ETILE + e_loc;
            int si = 0, di = 0;
            if (eg < n_edges) { si = __ldg(&g_src32[eg]); di = __ldg(&g_dst32[eg]); }
            const __half* us = &g_P16[(size_t)si * 256 + q * 16];
            const __half* vs = &g_P16[(size_t)di * 256 + 128 + q * 16];
            uint32_t ud = sbase + s * STAGE_BYTES + e_loc * U_PITCH_B + q * 32;
            uint32_t vd = ud + 17408;
            cp16(ud,      us);
            cp16(ud + 16, us + 8);
            cp16(vd,      vs);
            cp16(vd + 16, vs + 8);
        }
        cp_commit();
    };

    const int lrow = lane & 15;
    const int lkof = (lane >> 4) * 16;
    const uint32_t a_off = (uint32_t)(arow0 + lrow) * U_PITCH_B + lkof;

    int stage = 0;
    prefetch(blockIdx.x, 0);
    prefetch(blockIdx.x + G, 1);

    for (int t = blockIdx.x; t < n_tiles; t += G) {
        prefetch(t + 2 * G, (stage + 2) % 3);
        cp_wait2();
        __syncthreads();

        const uint32_t ub = sbase + stage * STAGE_BYTES + a_off;
        const uint32_t vb = ub + 17408;

        float c[3][4];
        #pragma unroll
        for (int j = 0; j < 3; j++)
            #pragma unroll
            for (int r = 0; r < 4; r++) c[j][r] = 0.f;

        #pragma unroll
        for (int kk = 0; kk < 8; kk++) {
            uint32_t au[4], av[4], a[4];
            ldmx4(au, ub + kk * 32);
            ldmx4(av, vb + kk * 32);
            #pragma unroll
            for (int r = 0; r < 4; r++)
                a[r] = hrelu2_(hadd2_(au[r], av[r]));
            #pragma unroll
            for (int j = 0; j < 3; j++)
                mma_f16(c[j], a, bf[j][kk]);
        }
        __syncthreads();

        {
            const int row = arow0 + (lane >> 2);
            #pragma unroll
            for (int j = 0; j < 3; j++) {
                int col = wc * 24 + j * 8 + 2 * (lane & 3);
                if (col < CN) {
                    OUTS[row * CN + col]       = c[j][0] + bias[j][0];
                    OUTS[(row + 8) * CN + col] = c[j][2] + bias[j][0];
                }
                if (col + 1 < CN) {
                    OUTS[row * CN + col + 1]       = c[j][1] + bias[j][1];
                    OUTS[(row + 8) * CN + col + 1] = c[j][3] + bias[j][1];
                }
            }
        }
        __syncthreads();

        int e0 = t * ETILE;
        int valid = n_edges - e0;
        if (valid > ETILE) valid = ETILE;
        float* dstp = out + (size_t)e0 * CN;
        if (valid == ETILE) {
            const float4* s4 = reinterpret_cast<const float4*>(OUTS);
            float4* d4 = reinterpret_cast<float4*>(dstp);
            #pragma unroll
            for (int i = tid; i < ETILE * CN / 4; i += ETHREADS) d4[i] = s4[i];
        } else {
            for (int i = tid; i < valid * CN; i += ETHREADS) dstp[i] = OUTS[i];
        }
        __syncthreads();
        stage = (stage + 1) % 3;
    }
    cp_wait0();
}

// ---------------------------------------------------------------------------
extern "C" void kernel_launch(void* const* d_in, const int* in_sizes, int n_in,
                              void* d_out, int out_size)
{
    const float* h   = (const float*)d_in[0];
    const float* W1  = (const float*)d_in[1];
    const float* b1  = (const float*)d_in[2];
    const float* W2  = (const float*)d_in[3];
    const float* b2  = (const float*)d_in[4];
    const void*  src = d_in[5];
    const void*  dst = d_in[6];
    float* out = (float*)d_out;

    const int n_nodes = in_sizes[0] / DN;
    const int n_edges = in_sizes[5];

    static int n_sm = 0;
    if (n_sm == 0) {
        cudaDeviceGetAttribute(&n_sm, cudaDevAttrMultiProcessorCount, 0);
        if (n_sm <= 0) n_sm = 148;
    }

    sniff_kernel<<<1, 256>>>(src, n_edges, n_nodes);
    convert_kernel<<<(n_edges + 255) / 256, 256>>>(src, dst, n_edges);
    w2h_kernel<<<(NP * DN + 255) / 256, 256>>>(W2);
    int n_helem = n_nodes * DN;
    h16_kernel<<<(n_helem / 4 + 255) / 256, 256>>>(h, n_helem);

    cudaFuncSetAttribute(node_mma_kernel, cudaFuncAttributeMaxDynamicSharedMemorySize, SMEM_NODE_BYTES);
    cudaFuncSetAttribute(edge_mma_kernel, cudaFuncAttributeMaxDynamicSharedMemorySize, SMEM_EDGE_BYTES);

    int n_tiles_node = (n_nodes + 63) / 64;
    node_mma_kernel<<<n_sm, 512, SMEM_NODE_BYTES>>>(W1, b1, n_nodes, n_tiles_node);

    int n_tiles = (n_edges + ETILE - 1) / ETILE;
    edge_mma_kernel<<<n_sm, ETHREADS, SMEM_EDGE_BYTES>>>(b2, out, n_edges, n_tiles);
}